// round 12
// baseline (speedup 1.0000x reference)
#include <cuda_runtime.h>
#include <cstdint>

// Embedding gather, persistent + register double-buffered (sm_103a).
// x: [32768] int32; emb: [50257, 512] f32; out: [32768, 512] f32.
// even ids -> id 0 (reference: jnp.where(x % 2 == 0, 0, x)).
//
// No smem, no barriers. Each CTA grid-strides over 16-row tiles.
// Loop body: issue next tile's 8 LDG.128 into buffer u, then store current
// buffer v. Stores don't depend on the new loads, so ~8 loads stay in
// flight per warp across the store phase -> load latency fully overlapped
// after the one-time prologue.

static constexpr int VEC_PER_ROW = 128;  // float4 per row
static constexpr int TILE_ROWS   = 16;
static constexpr int THREADS     = 256;
static constexpr int GRID        = 296;  // 2 CTAs/SM on 148 SMs

struct Tile { float4 a[8]; };

// chunk c covers rows {2c, 2c+1} of the tile: threads 0..127 -> row 2c,
// threads 128..255 -> row 2c+1; col = tid & 127 (fully coalesced).
__device__ __forceinline__ void load_tile(Tile& T,
                                          const int* __restrict__ x,
                                          const float4* __restrict__ emb,
                                          int row_base, int rhi, int col) {
#pragma unroll
    for (int c = 0; c < 8; c++) {
        int tok = __ldg(x + row_base + 2 * c + rhi);   // warp-uniform bcast
        tok = (tok & 1) ? tok : 0;                     // even ids -> row 0
        T.a[c] = __ldg(emb + (size_t)tok * VEC_PER_ROW + col);
    }
}

__device__ __forceinline__ void store_tile(const Tile& T,
                                           float4* __restrict__ out,
                                           int row_base, int tid) {
    float4* dst = out + (size_t)row_base * VEC_PER_ROW + tid;
#pragma unroll
    for (int c = 0; c < 8; c++)
        dst[c * THREADS] = T.a[c];
}

__global__ __launch_bounds__(THREADS)
void embed_gather_kernel(const int* __restrict__ x,
                         const float4* __restrict__ emb,
                         float4* __restrict__ out,
                         int n_tiles) {
    const int tid = threadIdx.x;
    const int rhi = tid >> 7;
    const int col = tid & 127;
    const int stride = gridDim.x;

    int t = blockIdx.x;
    if (t >= n_tiles) return;

    Tile v;
    load_tile(v, x, emb, t * TILE_ROWS, rhi, col);

    for (;;) {
        const int tn = t + stride;
        if (tn < n_tiles) {
            Tile u;
            load_tile(u, x, emb, tn * TILE_ROWS, rhi, col);  // in flight...
            store_tile(v, out, t * TILE_ROWS, tid);          // ...over these
            v = u;
            t = tn;
        } else {
            store_tile(v, out, t * TILE_ROWS, tid);
            break;
        }
    }
}

extern "C" void kernel_launch(void* const* d_in, const int* in_sizes, int n_in,
                              void* d_out, int out_size) {
    const int* x      = (const int*)d_in[0];
    const float4* emb = (const float4*)d_in[1];
    float4* out       = (float4*)d_out;

    int n_rows  = in_sizes[0];            // 32768
    int n_tiles = n_rows / TILE_ROWS;     // 2048

    embed_gather_kernel<<<GRID, THREADS>>>(x, emb, out, n_tiles);
}

// round 13
// speedup vs baseline: 1.5517x; 1.5517x over previous
#include <cuda_runtime.h>
#include <cstdint>

// Embedding gather — barrier-free, smem-free variant of the best (R3) shape.
// x: [32768] int32; emb: [50257, 512] f32; out: [32768, 512] f32.
// even ids -> id 0 (reference: jnp.where(x % 2 == 0, 0, x)).
//
// 512 threads/CTA, 32 rows/CTA, 8 float4 copies per thread.
// Chunk c covers rows {4c + tid>>7}: each warp's row id is warp-uniform,
// so ids are fetched via broadcast __ldg (1 wavefront, L1-hot) instead of
// a smem stage + __syncthreads. No smem, no BAR, single-phase CTA.

static constexpr int VEC_PER_ROW    = 128;  // float4 per row
static constexpr int ROWS_PER_BLOCK = 32;
static constexpr int THREADS        = 512;

__global__ __launch_bounds__(THREADS)
void embed_gather_kernel(const int* __restrict__ x,
                         const float4* __restrict__ emb,
                         float4* __restrict__ out) {
    const int base = blockIdx.x * ROWS_PER_BLOCK;
    const int tid  = threadIdx.x;

    // chunk c covers rows {4c .. 4c+3}: thread group tid>>7 (0..3) owns row
    // 4c + (tid>>7); col = tid & 127 (fully coalesced 128B per warp).
    const int rhi = tid >> 7;         // 0..3
    const int col = tid & 127;

    const int* xb = x + base + rhi;

    // Warp-uniform broadcast id loads (all 32 lanes same address, L1-hot).
    int t0 = __ldg(xb +  0);
    int t1 = __ldg(xb +  4);
    int t2 = __ldg(xb +  8);
    int t3 = __ldg(xb + 12);
    int t4 = __ldg(xb + 16);
    int t5 = __ldg(xb + 20);
    int t6 = __ldg(xb + 24);
    int t7 = __ldg(xb + 28);

    t0 = (t0 & 1) ? t0 : 0;   // even ids -> row 0
    t1 = (t1 & 1) ? t1 : 0;
    t2 = (t2 & 1) ? t2 : 0;
    t3 = (t3 & 1) ? t3 : 0;
    t4 = (t4 & 1) ? t4 : 0;
    t5 = (t5 & 1) ? t5 : 0;
    t6 = (t6 & 1) ? t6 : 0;
    t7 = (t7 & 1) ? t7 : 0;

    // 8 independent gathers (proven MLP-8 read path).
    float4 v0 = __ldg(emb + (size_t)t0 * VEC_PER_ROW + col);
    float4 v1 = __ldg(emb + (size_t)t1 * VEC_PER_ROW + col);
    float4 v2 = __ldg(emb + (size_t)t2 * VEC_PER_ROW + col);
    float4 v3 = __ldg(emb + (size_t)t3 * VEC_PER_ROW + col);
    float4 v4 = __ldg(emb + (size_t)t4 * VEC_PER_ROW + col);
    float4 v5 = __ldg(emb + (size_t)t5 * VEC_PER_ROW + col);
    float4 v6 = __ldg(emb + (size_t)t6 * VEC_PER_ROW + col);
    float4 v7 = __ldg(emb + (size_t)t7 * VEC_PER_ROW + col);

    // Store: chunk c writes flat float4 index c*512 + tid of the CTA tile.
    float4* dst = out + (size_t)base * VEC_PER_ROW + tid;
    dst[0 * THREADS] = v0;
    dst[1 * THREADS] = v1;
    dst[2 * THREADS] = v2;
    dst[3 * THREADS] = v3;
    dst[4 * THREADS] = v4;
    dst[5 * THREADS] = v5;
    dst[6 * THREADS] = v6;
    dst[7 * THREADS] = v7;
}

extern "C" void kernel_launch(void* const* d_in, const int* in_sizes, int n_in,
                              void* d_out, int out_size) {
    const int* x      = (const int*)d_in[0];
    const float4* emb = (const float4*)d_in[1];
    float4* out       = (float4*)d_out;

    int n_rows   = in_sizes[0];                 // 32768 (multiple of 32)
    int n_blocks = n_rows / ROWS_PER_BLOCK;     // 1024

    embed_gather_kernel<<<n_blocks, THREADS>>>(x, emb, out);
}